// round 3
// baseline (speedup 1.0000x reference)
#include <cuda_runtime.h>
#include <math.h>

// ---------------- problem constants ----------------
#define NMAT 8193
#define NI   8192
#define KCORR 2048u
#define MAXC 8192
#define NGRID 52
#define CAP  (1u << 21)      // candidate buffer entries
#define CAP2 (1u << 17)      // selected buffer entries
#define CHUNK 16384u
#define NCHUNK 4097u         // ceil(8192*8193 / 16384)
#define STAGE 2048
#define NBLOCKS 592          // 148 SMs x 4 co-resident blocks (guaranteed by launch_bounds)
#define NTHREADS 256

// ---------------- device scratch ----------------
__device__ float    g_cand_v[CAP];
__device__ int      g_cand_idx[CAP];
__device__ float    g_sel_v[CAP2];
__device__ int      g_sel_idx[CAP2];
__device__ float    g_lr[NI + 1];   // log(ref); [NI] = -1e30 sentinel (dustbin row)
__device__ float    g_ls[NI + 1];   // log(src); [NI] = -1e30 sentinel (dustbin col)
__device__ unsigned g_cand_count, g_cand_ovf, g_sel_count;
__device__ unsigned g_hist[49], g_hist2[49], g_c49, g_c50;
__device__ float    g_grid[NGRID];
__device__ float    g_wcap, g_W48m, g_W49p, g_W49m, g_W50p, g_W50m;
__device__ int      g_t50pos;
__device__ unsigned g_work1, g_work2, g_work3;
__device__ unsigned g_arrive;       // grid-barrier arrival counter (reset by k_prep)

// ---------------- prep: logs, grid, reset all state ----------------
__global__ void k_prep(const float* __restrict__ refw, const float* __restrict__ srcw) {
    int gid = blockIdx.x * blockDim.x + threadIdx.x;
    if (gid < NI) {
        g_lr[gid] = logf(refw[gid]);
        g_ls[gid] = logf(srcw[gid]);
    }
    if (gid == NI) { g_lr[NI] = -1e30f; g_ls[NI] = -1e30f; }
    if (gid < 49) { g_hist[gid] = 0; g_hist2[gid] = 0; }
    if (gid == 0) {
        g_cand_count = 0; g_cand_ovf = 0; g_sel_count = 0;
        g_c49 = 0; g_c50 = 0;
        g_work1 = 0; g_work2 = 0; g_work3 = 0;
        g_arrive = 0;
        float t = 0.5f;
        for (int k = 0; k < NGRID; k++) { g_grid[k] = t; t -= 0.01f; }
        g_wcap = logf(g_grid[44]) - 0.02f;   // capture cutoff in log domain
        float t48 = g_grid[48], t49 = g_grid[49], t50 = g_grid[50];
        g_W48m = logf(t48) - 0.005f;
        g_W49p = logf(t49) + 0.005f;
        g_W49m = logf(t49) - 0.005f;
        if (t50 > 0.0f) {
            g_t50pos = 1;
            g_W50p = logf(t50) + 0.005f;
            g_W50m = logf(t50) - 0.005f;
        } else { g_t50pos = 0; g_W50p = 0.0f; g_W50m = 0.0f; }
    }
}

// ---------------- software grid barrier (monotonic; reset each run by k_prep) ----
__device__ __forceinline__ void gsync(unsigned round) {
    __syncthreads();
    if (threadIdx.x == 0) {
        __threadfence();
        atomicAdd(&g_arrive, 1u);
        unsigned target = round * (unsigned)NBLOCKS;
        volatile unsigned* va = &g_arrive;
        while (*va < target) {}
        __threadfence();
    }
    __syncthreads();
}

// ---------------- the one persistent kernel ----------------
__global__ void __launch_bounds__(NTHREADS, 4)
k_main(const float* __restrict__ sc, const float* __restrict__ refw,
       const float* __restrict__ srcw, float* __restrict__ out) {
    __shared__ float    sv[STAGE];
    __shared__ int      si[STAGE];
    __shared__ unsigned sh[49];
    __shared__ float    gs[49];
    __shared__ unsigned s_cnt, s_base, s_ncnt, s_chunk;
    __shared__ float    s_thr;
    __shared__ int      s_need;

    const unsigned tid = threadIdx.x;
    if (tid < 49) { sh[tid] = 0; gs[tid] = g_grid[tid]; }
    const float wcap = g_wcap;
    const float4* __restrict__ p4 = (const float4*)sc;

    // ================= Phase 1: scan + candidate capture + block hist =========
    for (;;) {
        if (tid == 0) { s_chunk = atomicAdd(&g_work1, 1u); s_cnt = 0; }
        __syncthreads();
        unsigned c = s_chunk;
        if (c >= NCHUNK) break;
        unsigned start = c * CHUNK;
        unsigned r0 = start / 8193u;
        unsigned b1 = (r0 + 1u) * 8193u, b2 = b1 + 8193u;
        float lr0 = g_lr[r0];
        float lr1 = g_lr[r0 + 1u <= (unsigned)NI ? r0 + 1u : (unsigned)NI];
        float lr2 = g_lr[r0 + 2u <= (unsigned)NI ? r0 + 2u : (unsigned)NI];
        float cthr = wcap - fmaxf(lr0, fmaxf(lr1, lr2)) - 1e-3f;

#pragma unroll
        for (int k = 0; k < 4; k++) {
            unsigned e0 = start + (unsigned)k * 4096u + tid * 16u;
            unsigned q = e0 >> 2;
            float4 d0 = p4[q + 0];
            float4 d1 = p4[q + 1];
            float4 d2 = p4[q + 2];
            float4 d3 = p4[q + 3];
            float m0 = fmaxf(fmaxf(d0.x, d0.y), fmaxf(d0.z, d0.w));
            float m1 = fmaxf(fmaxf(d1.x, d1.y), fmaxf(d1.z, d1.w));
            float m2 = fmaxf(fmaxf(d2.x, d2.y), fmaxf(d2.z, d2.w));
            float m3 = fmaxf(fmaxf(d3.x, d3.y), fmaxf(d3.z, d3.w));
            float mm = fmaxf(fmaxf(m0, m1), fmaxf(m2, m3));
            if (mm > cthr) {
#pragma unroll
                for (int qq = 0; qq < 4; qq++) {
                    float mq = (qq == 0) ? m0 : (qq == 1) ? m1 : (qq == 2) ? m2 : m3;
                    if (mq > cthr) {
                        float4 d = (qq == 0) ? d0 : (qq == 1) ? d1 : (qq == 2) ? d2 : d3;
                        unsigned eq = e0 + (unsigned)qq * 4u;
#pragma unroll
                        for (int ii = 0; ii < 4; ii++) {
                            float s = (ii == 0) ? d.x : (ii == 1) ? d.y : (ii == 2) ? d.z : d.w;
                            if (s > cthr) {
                                unsigned e = eq + (unsigned)ii;
                                int ge1 = (e >= b1), ge2 = (e >= b2);
                                unsigned r = r0 + (unsigned)ge1 + (unsigned)ge2;
                                float lr = ge2 ? lr2 : (ge1 ? lr1 : lr0);
                                unsigned cc = e - r * 8193u;
                                float w = s + (lr + g_ls[cc]);
                                if (w > wcap) {
                                    float v = expf(s) * (refw[r] * srcw[cc]);
                                    unsigned slot = atomicAdd(&s_cnt, 1u);
                                    if (slot < (unsigned)STAGE) {
                                        sv[slot] = v;
                                        si[slot] = ((int)r << 13) | (int)cc;
                                    }
                                }
                            }
                        }
                    }
                }
            }
        }
        __syncthreads();
        if (tid == 0) {
            unsigned n = s_cnt;
            unsigned nc = n < (unsigned)STAGE ? n : (unsigned)STAGE;
            if (n > (unsigned)STAGE) atomicExch(&g_cand_ovf, 1u);
            s_base = nc ? atomicAdd(&g_cand_count, nc) : 0u;
            s_ncnt = nc;
        }
        __syncthreads();
        unsigned nc = s_ncnt, gb = s_base;
        float t48 = gs[48];
        for (unsigned i = tid; i < nc; i += NTHREADS) {
            float v = sv[i]; int ix = si[i];
            unsigned slot = gb + i;
            if (slot < CAP) { g_cand_v[slot] = v; g_cand_idx[slot] = ix; }
            if (v > t48) {
                int lo = 0, hi = 48;
                while (lo < hi) { int mid = (lo + hi) >> 1; if (gs[mid] < v) hi = mid; else lo = mid + 1; }
                atomicAdd(&sh[lo], 1u);
            }
        }
    }
    if (tid < 49 && sh[tid]) atomicAdd(&g_hist[tid], sh[tid]);
    gsync(1);

    // ================= threshold (computed locally per block) ==================
    if (tid == 0) {
        unsigned cum = 0; int kstar = -1;
        for (int k = 0; k <= 44; k++) { cum += g_hist[k]; if (cum >= KCORR) { kstar = k; break; } }
        bool bad = (g_cand_ovf != 0u) || (g_cand_count > CAP) || (kstar < 0);
        s_need = bad ? 1 : 0;
        s_thr = (kstar >= 0) ? gs[kstar] : 0.0f;
    }
    __syncthreads();

    if (!s_need) {
        // ============== primary select + output defaults ======================
        float thr = s_thr;
        unsigned gtid = blockIdx.x * NTHREADS + tid;
        if (gtid < 2u * MAXC)      out[gtid] = -1.0f;
        else if (gtid < 3u * MAXC) out[gtid] = 0.0f;

        unsigned n = g_cand_count; if (n > CAP) n = CAP;
        unsigned total = NBLOCKS * NTHREADS;
        unsigned lane = tid & 31u;
        unsigned wbase = gtid - lane;
        for (unsigned b = wbase; b < n; b += total) {
            unsigned i = b + lane;
            bool pred = false; float v = 0.0f; int ix = 0;
            if (i < n) { v = g_cand_v[i]; ix = g_cand_idx[i]; pred = (v > thr); }
            unsigned m = __ballot_sync(0xffffffffu, pred);
            if (m) {
                unsigned base;
                int leader = __ffs(m) - 1;
                if ((int)lane == leader) base = atomicAdd(&g_sel_count, (unsigned)__popc(m));
                base = __shfl_sync(0xffffffffu, base, leader);
                if (pred) {
                    unsigned slot = base + __popc(m & ((1u << lane) - 1u));
                    if (slot < CAP2) { g_sel_v[slot] = v; g_sel_idx[slot] = ix; }
                }
            }
        }
        gsync(2);
    } else {
        // ============== fallback: exact full histogram =========================
        if (tid < 49) sh[tid] = 0;
        float t48 = gs[48], t49 = g_grid[49], t50 = g_grid[50];
        float W48m = g_W48m, W49p = g_W49p, W49m = g_W49m, W50p = g_W50p, W50m = g_W50m;
        int t50pos = g_t50pos;
        unsigned c49 = 0, c50 = 0;
        for (;;) {
            if (tid == 0) s_chunk = atomicAdd(&g_work2, 1u);
            __syncthreads();
            unsigned c = s_chunk;
            if (c >= NCHUNK) break;
            unsigned start = c * CHUNK;
            unsigned r0 = start / 8193u;
            unsigned b1 = (r0 + 1u) * 8193u, b2 = b1 + 8193u;
            float lr0 = g_lr[r0];
            float lr1 = g_lr[r0 + 1u <= (unsigned)NI ? r0 + 1u : (unsigned)NI];
            float lr2 = g_lr[r0 + 2u <= (unsigned)NI ? r0 + 2u : (unsigned)NI];
            for (int k = 0; k < 4; k++) {
                unsigned e0 = start + (unsigned)k * 4096u + tid * 16u;
                for (int ii = 0; ii < 16; ii++) {
                    unsigned e = e0 + (unsigned)ii;
                    float s = sc[e];
                    int ge1 = (e >= b1), ge2 = (e >= b2);
                    unsigned r = r0 + (unsigned)ge1 + (unsigned)ge2;
                    float lr = ge2 ? lr2 : (ge1 ? lr1 : lr0);
                    unsigned cc = e - r * 8193u;
                    float w = s + (lr + g_ls[cc]);
                    float v = 0.0f; bool havev = false;
                    if (w > W48m) {
                        v = expf(s) * (refw[r] * srcw[cc]); havev = true;
                        if (v > t48) {
                            int lo = 0, hi = 48;
                            while (lo < hi) { int mid = (lo + hi) >> 1; if (gs[mid] < v) hi = mid; else lo = mid + 1; }
                            atomicAdd(&sh[lo], 1u);
                        }
                    }
                    if (w > W49p) c49++;
                    else if (w > W49m) {
                        if (!havev) { v = expf(s) * (refw[r] * srcw[cc]); havev = true; }
                        if (v > t49) c49++;
                    }
                    if (t50pos) {
                        if (w > W50p) c50++;
                        else if (w > W50m) {
                            if (!havev) { v = expf(s) * (refw[r] * srcw[cc]); }
                            if (v > t50) c50++;
                        }
                    } else c50++;
                }
            }
        }
        if (c49) atomicAdd(&g_c49, c49);
        if (c50) atomicAdd(&g_c50, c50);
        if (tid < 49 && sh[tid]) atomicAdd(&g_hist2[tid], sh[tid]);
        gsync(2);

        if (tid == 0) {
            unsigned cum = 0; int kstar = -1;
            for (int k = 0; k <= 48; k++) { cum += g_hist2[k]; if (cum >= KCORR) { kstar = k; break; } }
            if (kstar < 0) {
                if (g_c49 >= KCORR) kstar = 49;
                else if (g_c50 >= KCORR) kstar = 50;
                else kstar = 51;
            }
            s_thr = g_grid[kstar];
        }
        __syncthreads();
        float thr = s_thr;
        float wf = (thr > 0.0f) ? (logf(thr) - 0.005f) : -3.0e38f;

        // defaults
        unsigned gtid = blockIdx.x * NTHREADS + tid;
        if (gtid < 2u * MAXC)      out[gtid] = -1.0f;
        else if (gtid < 3u * MAXC) out[gtid] = 0.0f;

        // full-matrix select
        for (;;) {
            if (tid == 0) { s_chunk = atomicAdd(&g_work3, 1u); s_cnt = 0; }
            __syncthreads();
            unsigned c = s_chunk;
            if (c >= NCHUNK) break;
            unsigned start = c * CHUNK;
            unsigned r0 = start / 8193u;
            unsigned b1 = (r0 + 1u) * 8193u, b2 = b1 + 8193u;
            float lr0 = g_lr[r0];
            float lr1 = g_lr[r0 + 1u <= (unsigned)NI ? r0 + 1u : (unsigned)NI];
            float lr2 = g_lr[r0 + 2u <= (unsigned)NI ? r0 + 2u : (unsigned)NI];
            for (int k = 0; k < 4; k++) {
                unsigned e0 = start + (unsigned)k * 4096u + tid * 16u;
                for (int ii = 0; ii < 16; ii++) {
                    unsigned e = e0 + (unsigned)ii;
                    float s = sc[e];
                    int ge1 = (e >= b1), ge2 = (e >= b2);
                    unsigned r = r0 + (unsigned)ge1 + (unsigned)ge2;
                    float lr = ge2 ? lr2 : (ge1 ? lr1 : lr0);
                    unsigned cc = e - r * 8193u;
                    float w = s + (lr + g_ls[cc]);
                    if (w > wf) {
                        float v = expf(s) * (refw[r] * srcw[cc]);
                        if (v > thr) {
                            unsigned slot = atomicAdd(&s_cnt, 1u);
                            if (slot < (unsigned)STAGE) {
                                sv[slot] = v;
                                si[slot] = ((int)r << 13) | (int)cc;
                            }
                        }
                    }
                }
            }
            __syncthreads();
            if (tid == 0) {
                unsigned nn = s_cnt;
                unsigned ncl = nn < (unsigned)STAGE ? nn : (unsigned)STAGE;
                s_base = ncl ? atomicAdd(&g_sel_count, ncl) : 0u;
                s_ncnt = ncl;
            }
            __syncthreads();
            unsigned ncl = s_ncnt, gb = s_base;
            for (unsigned i = tid; i < ncl; i += NTHREADS) {
                unsigned slot = gb + i;
                if (slot < CAP2) { g_sel_v[slot] = sv[i]; g_sel_idx[slot] = si[i]; }
            }
        }
        gsync(3);
    }

    // ================= rank (row-major order) + write ==========================
    unsigned S = g_sel_count; if (S > CAP2) S = CAP2;
    unsigned t = blockIdx.x * NTHREADS + tid;
    if (blockIdx.x * NTHREADS >= S) return;   // idle block (after last barrier)
    bool act = (t < S);
    int   my = 0; float v = 0.0f;
    if (act) { my = g_sel_idx[t]; v = g_sel_v[t]; }
    unsigned rank = 0;
    for (unsigned base = 0; base < S; base += (unsigned)STAGE) {
        unsigned n = S - base; if (n > (unsigned)STAGE) n = (unsigned)STAGE;
        __syncthreads();
        for (unsigned i = tid; i < n; i += NTHREADS) si[i] = g_sel_idx[base + i];
        __syncthreads();
        if (act) {
            unsigned i = 0;
            for (; i + 4 <= n; i += 4)
                rank += (si[i] < my) + (si[i+1] < my) + (si[i+2] < my) + (si[i+3] < my);
            for (; i < n; i++) rank += (si[i] < my);
        }
    }
    if (act && rank < MAXC) {
        out[rank]            = (float)(my >> 13);
        out[MAXC + rank]     = (float)(my & 8191);
        out[2 * MAXC + rank] = v;
    }
}

// ---------------- launch: exactly 2 kernels ----------------
extern "C" void kernel_launch(void* const* d_in, const int* in_sizes, int n_in,
                              void* d_out, int out_size) {
    const float* sc   = (const float*)d_in[0];
    const float* refw = (const float*)d_in[1];
    const float* srcw = (const float*)d_in[2];
    float* out = (float*)d_out;

    k_prep<<<64, 256>>>(refw, srcw);
    k_main<<<NBLOCKS, NTHREADS>>>(sc, refw, srcw, out);
}

// round 4
// speedup vs baseline: 1.4450x; 1.4450x over previous
#include <cuda_runtime.h>
#include <math.h>

// ---------------- problem constants ----------------
#define NMAT 8193
#define NI   8192
#define NQ4  16779264u        // (8192*8193)/4 flat float4 count
#define KCORR 2048u
#define MAXC 8192
#define NGRID 52
#define CAP   (1u << 21)      // candidate buffer entries
#define SCAP  3072u           // per-block (s,e) staging
#define CCAP  1024u           // per-block candidate staging
#define NBLOCKS 592
#define NTHREADS 256
#define TTOT 151552u          // NBLOCKS*NTHREADS
#define CHUNK 16384u          // fallback chunking
#define NCHUNK 4097u

// ---------------- device scratch ----------------
__device__ float    g_cand_v[CAP];
__device__ int      g_cand_idx[CAP];
__device__ float    g_sel_v[CAP];
__device__ int      g_sel_idx[CAP];
__device__ float    g_lr[NI + 1];    // log(ref); [NI] = -1e30 sentinel
__device__ float    g_ls[NI + 1];    // log(src); [NI] = -1e30 sentinel (dustbin col)
__device__ unsigned g_maxkey_lr = 0; // monotone float keys; atomicMax idempotent across replays
__device__ unsigned g_maxkey_ls = 0;
__device__ unsigned g_cand_count, g_ovf, g_sel_count;
__device__ unsigned g_hist[49], g_hist2[49], g_c49, g_c50;
__device__ float    g_grid[NGRID];
__device__ float    g_wcap, g_W48m, g_W49p, g_W49m, g_W50p, g_W50m;
__device__ int      g_t50pos;
__device__ unsigned g_work2, g_work3;
__device__ unsigned g_arrive;

__device__ __forceinline__ unsigned fkey(float f) {
    unsigned b = __float_as_uint(f);
    return b ^ ((b & 0x80000000u) ? 0xFFFFFFFFu : 0x80000000u);
}
__device__ __forceinline__ float finv(unsigned k) {
    unsigned b = (k & 0x80000000u) ? (k ^ 0x80000000u) : ~k;
    return __uint_as_float(b);
}

// ---------------- prep ----------------
__global__ void k_prep(const float* __restrict__ refw, const float* __restrict__ srcw) {
    int gid = blockIdx.x * blockDim.x + threadIdx.x;
    if (gid < NI) {
        float lr = logf(refw[gid]);
        float ls = logf(srcw[gid]);
        g_lr[gid] = lr; g_ls[gid] = ls;
        atomicMax(&g_maxkey_lr, fkey(lr));
        atomicMax(&g_maxkey_ls, fkey(ls));
    }
    if (gid == NI) { g_lr[NI] = -1e30f; g_ls[NI] = -1e30f; }
    if (gid < 49) { g_hist[gid] = 0; g_hist2[gid] = 0; }
    if (gid == 0) {
        g_cand_count = 0; g_ovf = 0; g_sel_count = 0;
        g_c49 = 0; g_c50 = 0; g_work2 = 0; g_work3 = 0; g_arrive = 0;
        float t = 0.5f;
        for (int k = 0; k < NGRID; k++) { g_grid[k] = t; t -= 0.01f; }
        g_wcap = logf(g_grid[44]) - 0.02f;
        float t48 = g_grid[48], t49 = g_grid[49], t50 = g_grid[50];
        g_W48m = logf(t48) - 0.005f;
        g_W49p = logf(t49) + 0.005f;
        g_W49m = logf(t49) - 0.005f;
        if (t50 > 0.0f) { g_t50pos = 1; g_W50p = logf(t50) + 0.005f; g_W50m = logf(t50) - 0.005f; }
        else { g_t50pos = 0; g_W50p = 0.0f; g_W50m = 0.0f; }
    }
}

// ---------------- grid barrier (monotonic; reset each run by k_prep) ----------------
__device__ __forceinline__ void gsync(unsigned round) {
    __syncthreads();
    if (threadIdx.x == 0) {
        __threadfence();
        atomicAdd(&g_arrive, 1u);
        unsigned target = round * (unsigned)NBLOCKS;
        volatile unsigned* va = &g_arrive;
        while (*va < target) {}
        __threadfence();
    }
    __syncthreads();
}

// ---------------- hot-path quad processing ----------------
__device__ __forceinline__ void proc_quad(float4 d, unsigned qi, float cthr,
                                          float* s_st_s, unsigned* s_st_e, unsigned* s_cnt) {
    float mq = fmaxf(fmaxf(d.x, d.y), fmaxf(d.z, d.w));
    unsigned lane = threadIdx.x & 31u;
    unsigned hit = __ballot_sync(0xffffffffu, mq > cthr);
    if (!hit) return;
#pragma unroll
    for (int ii = 0; ii < 4; ii++) {
        float s = (ii == 0) ? d.x : (ii == 1) ? d.y : (ii == 2) ? d.z : d.w;
        bool p = s > cthr;
        unsigned m = __ballot_sync(0xffffffffu, p);
        if (m) {
            unsigned base;
            int leader = __ffs(m) - 1;
            if ((int)lane == leader) base = atomicAdd(s_cnt, (unsigned)__popc(m));
            base = __shfl_sync(0xffffffffu, base, leader);
            if (p) {
                unsigned slot = base + __popc(m & ((1u << lane) - 1u));
                if (slot < SCAP) { s_st_s[slot] = s; s_st_e[slot] = (qi << 2) + (unsigned)ii; }
            }
        }
    }
}

// ---------------- the persistent kernel ----------------
__global__ void __launch_bounds__(NTHREADS, 4)
k_main(const float* __restrict__ sc, const float* __restrict__ refw,
       const float* __restrict__ srcw, float* __restrict__ out) {
    __shared__ float    s_st_s[SCAP];
    __shared__ unsigned s_st_e[SCAP];
    __shared__ float    s_cv[CCAP];
    __shared__ int      s_ci[CCAP];
    __shared__ unsigned sh[49];
    __shared__ float    gs[49];
    __shared__ unsigned s_cnt, s_ccnt, s_base, s_n, s_chunk;
    __shared__ float    s_thr;
    __shared__ int      s_need;

    const unsigned tid = threadIdx.x;
    const unsigned lane = tid & 31u;
    const unsigned gtid = blockIdx.x * NTHREADS + tid;
    if (tid < 49) { sh[tid] = 0; gs[tid] = g_grid[tid]; }
    if (tid == 0) { s_cnt = 0; s_ccnt = 0; }
    const float wcap = g_wcap;
    const float cthr = wcap - (finv(g_maxkey_lr) + finv(g_maxkey_ls)) - 1e-4f;
    const float4* __restrict__ p4 = (const float4*)sc;
    __syncthreads();

    // ================= Phase 1: coalesced grid-stride scan =================
    {
        unsigned base = 0;
        for (; base + 4u * TTOT <= NQ4; base += 4u * TTOT) {
            unsigned q0 = base + gtid;
            float4 d0 = p4[q0];
            float4 d1 = p4[q0 + TTOT];
            float4 d2 = p4[q0 + 2u * TTOT];
            float4 d3 = p4[q0 + 3u * TTOT];
            proc_quad(d0, q0,             cthr, s_st_s, s_st_e, &s_cnt);
            proc_quad(d1, q0 + TTOT,      cthr, s_st_s, s_st_e, &s_cnt);
            proc_quad(d2, q0 + 2u * TTOT, cthr, s_st_s, s_st_e, &s_cnt);
            proc_quad(d3, q0 + 3u * TTOT, cthr, s_st_s, s_st_e, &s_cnt);
        }
        for (; base + TTOT <= NQ4; base += TTOT) {
            unsigned q0 = base + gtid;
            float4 d = p4[q0];
            proc_quad(d, q0, cthr, s_st_s, s_st_e, &s_cnt);
        }
        if (base < NQ4) {  // partial round, warp-uniform entry
            unsigned q0 = base + gtid;
            float4 d = make_float4(-1e30f, -1e30f, -1e30f, -1e30f);
            if (q0 < NQ4) d = p4[q0];
            proc_quad(d, q0, cthr, s_st_s, s_st_e, &s_cnt);
        }
    }
    __syncthreads();

    // ================= Phase 1b: process staged hits =================
    {
        unsigned nst = s_cnt;
        if (nst > SCAP) { if (tid == 0) atomicExch(&g_ovf, 1u); nst = SCAP; }
        float t48 = gs[48];
        for (unsigned i = tid; i < nst; i += NTHREADS) {
            float s = s_st_s[i];
            unsigned e = s_st_e[i];
            unsigned r = e / 8193u;
            unsigned c = e - r * 8193u;
            float w = s + (g_lr[r] + g_ls[c]);
            if (w > wcap) {
                float v = expf(s) * (refw[r] * srcw[c]);
                if (v > t48) {
                    int lo = 0, hi = 48;
                    while (lo < hi) { int mid = (lo + hi) >> 1; if (gs[mid] < v) hi = mid; else lo = mid + 1; }
                    atomicAdd(&sh[lo], 1u);
                }
                unsigned slot = atomicAdd(&s_ccnt, 1u);
                if (slot < CCAP) { s_cv[slot] = v; s_ci[slot] = ((int)r << 13) | (int)c; }
            }
        }
        __syncthreads();
        if (tid == 0) {
            unsigned nc = s_ccnt;
            if (nc > CCAP) { atomicExch(&g_ovf, 1u); nc = CCAP; }
            s_n = nc;
            s_base = nc ? atomicAdd(&g_cand_count, nc) : 0u;
        }
        __syncthreads();
        unsigned nc = s_n, gb = s_base;
        for (unsigned i = tid; i < nc; i += NTHREADS) {
            unsigned slot = gb + i;
            if (slot < CAP) { g_cand_v[slot] = s_cv[i]; g_cand_idx[slot] = s_ci[i]; }
        }
        if (tid < 49 && sh[tid]) atomicAdd(&g_hist[tid], sh[tid]);
    }
    gsync(1);

    // ================= threshold decision =================
    if (tid == 0) {
        unsigned cum = 0; int kstar = -1;
        for (int k = 0; k <= 44; k++) { cum += g_hist[k]; if (cum >= KCORR) { kstar = k; break; } }
        bool bad = (g_ovf != 0u) || (g_cand_count > CAP) || (kstar < 0);
        s_need = bad ? 1 : 0;
        s_thr = (kstar >= 0) ? gs[kstar] : 0.0f;
    }
    __syncthreads();

    if (!s_need) {
        // ============== primary select + output defaults ==============
        float thr = s_thr;
        if (gtid < 2u * MAXC)      out[gtid] = -1.0f;
        else if (gtid < 3u * MAXC) out[gtid] = 0.0f;

        unsigned n = g_cand_count;
        unsigned wbase = gtid - lane;
        for (unsigned b = wbase; b < n; b += TTOT) {
            unsigned i = b + lane;
            bool pred = false; float v = 0.0f; int ix = 0;
            if (i < n) { v = g_cand_v[i]; ix = g_cand_idx[i]; pred = (v > thr); }
            unsigned m = __ballot_sync(0xffffffffu, pred);
            if (m) {
                unsigned base;
                int leader = __ffs(m) - 1;
                if ((int)lane == leader) base = atomicAdd(&g_sel_count, (unsigned)__popc(m));
                base = __shfl_sync(0xffffffffu, base, leader);
                if (pred) {
                    unsigned slot = base + __popc(m & ((1u << lane) - 1u));
                    if (slot < CAP) { g_sel_v[slot] = v; g_sel_idx[slot] = ix; }
                }
            }
        }
        gsync(2);
    } else {
        // ============== fallback: exact full histogram ==============
        if (tid < 49) sh[tid] = 0;
        float t48 = gs[48], t49 = g_grid[49], t50 = g_grid[50];
        float W48m = g_W48m, W49p = g_W49p, W49m = g_W49m, W50p = g_W50p, W50m = g_W50m;
        int t50pos = g_t50pos;
        unsigned c49 = 0, c50 = 0;
        for (;;) {
            if (tid == 0) s_chunk = atomicAdd(&g_work2, 1u);
            __syncthreads();
            unsigned c = s_chunk;
            __syncthreads();
            if (c >= NCHUNK) break;
            unsigned start = c * CHUNK;
            unsigned r0 = start / 8193u;
            unsigned b1 = (r0 + 1u) * 8193u, b2 = b1 + 8193u;
            float lr0 = g_lr[r0];
            float lr1 = g_lr[r0 + 1u <= (unsigned)NI ? r0 + 1u : (unsigned)NI];
            float lr2 = g_lr[r0 + 2u <= (unsigned)NI ? r0 + 2u : (unsigned)NI];
            for (int k = 0; k < 4; k++) {
                unsigned e0 = start + (unsigned)k * 4096u + tid * 16u;
                for (int ii = 0; ii < 16; ii++) {
                    unsigned e = e0 + (unsigned)ii;
                    if (e >= 67117056u) continue;
                    float s = sc[e];
                    int ge1 = (e >= b1), ge2 = (e >= b2);
                    unsigned r = r0 + (unsigned)ge1 + (unsigned)ge2;
                    float lr = ge2 ? lr2 : (ge1 ? lr1 : lr0);
                    unsigned cc = e - r * 8193u;
                    float w = s + (lr + g_ls[cc]);
                    float v = 0.0f; bool havev = false;
                    if (w > W48m) {
                        v = expf(s) * (refw[r] * srcw[cc]); havev = true;
                        if (v > t48) {
                            int lo = 0, hi = 48;
                            while (lo < hi) { int mid = (lo + hi) >> 1; if (gs[mid] < v) hi = mid; else lo = mid + 1; }
                            atomicAdd(&sh[lo], 1u);
                        }
                    }
                    if (w > W49p) c49++;
                    else if (w > W49m) {
                        if (!havev) { v = expf(s) * (refw[r] * srcw[cc]); havev = true; }
                        if (v > t49) c49++;
                    }
                    if (t50pos) {
                        if (w > W50p) c50++;
                        else if (w > W50m) {
                            if (!havev) { v = expf(s) * (refw[r] * srcw[cc]); }
                            if (v > t50) c50++;
                        }
                    } else c50++;
                }
            }
        }
        if (c49) atomicAdd(&g_c49, c49);
        if (c50) atomicAdd(&g_c50, c50);
        if (tid < 49 && sh[tid]) atomicAdd(&g_hist2[tid], sh[tid]);
        gsync(2);

        if (tid == 0) {
            unsigned cum = 0; int kstar = -1;
            for (int k = 0; k <= 48; k++) { cum += g_hist2[k]; if (cum >= KCORR) { kstar = k; break; } }
            if (kstar < 0) {
                if (g_c49 >= KCORR) kstar = 49;
                else if (g_c50 >= KCORR) kstar = 50;
                else kstar = 51;
            }
            s_thr = g_grid[kstar];
        }
        __syncthreads();
        float thr = s_thr;
        float wf = (thr > 0.0f) ? (logf(thr) - 0.005f) : -3.0e38f;

        if (gtid < 2u * MAXC)      out[gtid] = -1.0f;
        else if (gtid < 3u * MAXC) out[gtid] = 0.0f;

        // full-matrix select (reuses staging arrays)
        for (;;) {
            if (tid == 0) { s_chunk = atomicAdd(&g_work3, 1u); s_cnt = 0; }
            __syncthreads();
            unsigned c = s_chunk;
            if (c >= NCHUNK) break;
            unsigned start = c * CHUNK;
            unsigned r0 = start / 8193u;
            unsigned b1 = (r0 + 1u) * 8193u, b2 = b1 + 8193u;
            float lr0 = g_lr[r0];
            float lr1 = g_lr[r0 + 1u <= (unsigned)NI ? r0 + 1u : (unsigned)NI];
            float lr2 = g_lr[r0 + 2u <= (unsigned)NI ? r0 + 2u : (unsigned)NI];
            for (int k = 0; k < 4; k++) {
                unsigned e0 = start + (unsigned)k * 4096u + tid * 16u;
                for (int ii = 0; ii < 16; ii++) {
                    unsigned e = e0 + (unsigned)ii;
                    if (e >= 67117056u) continue;
                    float s = sc[e];
                    int ge1 = (e >= b1), ge2 = (e >= b2);
                    unsigned r = r0 + (unsigned)ge1 + (unsigned)ge2;
                    float lr = ge2 ? lr2 : (ge1 ? lr1 : lr0);
                    unsigned cc = e - r * 8193u;
                    float w = s + (lr + g_ls[cc]);
                    if (w > wf) {
                        float v = expf(s) * (refw[r] * srcw[cc]);
                        if (v > thr) {
                            unsigned slot = atomicAdd(&s_cnt, 1u);
                            if (slot < SCAP) { s_st_s[slot] = v; s_st_e[slot] = (r << 13) | cc; }
                        }
                    }
                }
            }
            __syncthreads();
            if (tid == 0) {
                unsigned nn = s_cnt;
                unsigned ncl = nn < SCAP ? nn : SCAP;
                s_base = ncl ? atomicAdd(&g_sel_count, ncl) : 0u;
                s_n = ncl;
            }
            __syncthreads();
            unsigned ncl = s_n, gb = s_base;
            for (unsigned i = tid; i < ncl; i += NTHREADS) {
                unsigned slot = gb + i;
                if (slot < CAP) { g_sel_v[slot] = s_st_s[i]; g_sel_idx[slot] = (int)s_st_e[i]; }
            }
            __syncthreads();
        }
        gsync(3);
    }

    // ================= rank (row-major order) + write =================
    unsigned S = g_sel_count; if (S > CAP) S = CAP;
    unsigned t = gtid;
    if (blockIdx.x * NTHREADS >= S) return;
    bool act = (t < S);
    int my = 0; float v = 0.0f;
    if (act) { my = g_sel_idx[t]; v = g_sel_v[t]; }
    int* tile = (int*)s_st_e;
    unsigned rank = 0;
    for (unsigned base = 0; base < S; base += SCAP) {
        unsigned n = S - base; if (n > SCAP) n = SCAP;
        __syncthreads();
        for (unsigned i = tid; i < n; i += NTHREADS) tile[i] = g_sel_idx[base + i];
        __syncthreads();
        if (act) {
            unsigned i = 0;
            for (; i + 4 <= n; i += 4)
                rank += (tile[i] < my) + (tile[i+1] < my) + (tile[i+2] < my) + (tile[i+3] < my);
            for (; i < n; i++) rank += (tile[i] < my);
        }
    }
    if (act && rank < MAXC) {
        out[rank]            = (float)(my >> 13);
        out[MAXC + rank]     = (float)(my & 8191);
        out[2 * MAXC + rank] = v;
    }
}

// ---------------- launch ----------------
extern "C" void kernel_launch(void* const* d_in, const int* in_sizes, int n_in,
                              void* d_out, int out_size) {
    const float* sc   = (const float*)d_in[0];
    const float* refw = (const float*)d_in[1];
    const float* srcw = (const float*)d_in[2];
    float* out = (float*)d_out;

    k_prep<<<64, 256>>>(refw, srcw);
    k_main<<<NBLOCKS, NTHREADS>>>(sc, refw, srcw, out);
}

// round 5
// speedup vs baseline: 1.9243x; 1.3317x over previous
#include <cuda_runtime.h>
#include <math.h>

// ---------------- problem constants ----------------
#define NMAT 8193
#define NI   8192
#define NQ4  16779264u        // (8192*8193)/4 flat float4 count
#define KCORR 2048u
#define MAXC 8192
#define NGRID 52
#define CAP   (1u << 21)      // candidate buffer entries
#define SCAP  3072u           // per-block (s,e) staging
#define CCAP  1024u           // per-block candidate staging
#define NBLOCKS 592
#define NTHREADS 256
#define TTOT 151552u          // NBLOCKS*NTHREADS
#define CHUNK 16384u          // fallback chunking
#define NCHUNK 4097u

// ---------------- device scratch ----------------
__device__ float    g_cand_v[CAP];
__device__ int      g_cand_idx[CAP];
__device__ float    g_sel_v[CAP];
__device__ int      g_sel_idx[CAP];
__device__ float    g_lr[NI + 1];    // log(ref); [NI] = -1e30 sentinel
__device__ float    g_ls[NI + 1];    // log(src); [NI] = -1e30 sentinel (dustbin col)
__device__ unsigned g_maxkey_lr = 0; // monotone float keys; atomicMax idempotent across replays
__device__ unsigned g_maxkey_ls = 0;
__device__ unsigned g_cand_count, g_ovf, g_sel_count;
__device__ unsigned g_hist[49], g_hist2[49], g_c49, g_c50;
__device__ float    g_grid[NGRID];
__device__ float    g_wcap, g_W48m, g_W49p, g_W49m, g_W50p, g_W50m;
__device__ int      g_t50pos;
__device__ unsigned g_work2, g_work3;
__device__ unsigned g_arrive;

__device__ __forceinline__ unsigned fkey(float f) {
    unsigned b = __float_as_uint(f);
    return b ^ ((b & 0x80000000u) ? 0xFFFFFFFFu : 0x80000000u);
}
__device__ __forceinline__ float finv(unsigned k) {
    unsigned b = (k & 0x80000000u) ? (k ^ 0x80000000u) : ~k;
    return __uint_as_float(b);
}

// ---------------- prep ----------------
__global__ void k_prep(const float* __restrict__ refw, const float* __restrict__ srcw) {
    int gid = blockIdx.x * blockDim.x + threadIdx.x;
    if (gid < NI) {
        float lr = logf(refw[gid]);
        float ls = logf(srcw[gid]);
        g_lr[gid] = lr; g_ls[gid] = ls;
        atomicMax(&g_maxkey_lr, fkey(lr));
        atomicMax(&g_maxkey_ls, fkey(ls));
    }
    if (gid == NI) { g_lr[NI] = -1e30f; g_ls[NI] = -1e30f; }
    if (gid < 49) { g_hist[gid] = 0; g_hist2[gid] = 0; }
    if (gid == 0) {
        g_cand_count = 0; g_ovf = 0; g_sel_count = 0;
        g_c49 = 0; g_c50 = 0; g_work2 = 0; g_work3 = 0; g_arrive = 0;
        float t = 0.5f;
        for (int k = 0; k < NGRID; k++) { g_grid[k] = t; t -= 0.01f; }
        g_wcap = logf(g_grid[44]) - 0.02f;
        float t48 = g_grid[48], t49 = g_grid[49], t50 = g_grid[50];
        g_W48m = logf(t48) - 0.005f;
        g_W49p = logf(t49) + 0.005f;
        g_W49m = logf(t49) - 0.005f;
        if (t50 > 0.0f) { g_t50pos = 1; g_W50p = logf(t50) + 0.005f; g_W50m = logf(t50) - 0.005f; }
        else { g_t50pos = 0; g_W50p = 0.0f; g_W50m = 0.0f; }
    }
}

// ---------------- grid barrier (monotonic; reset each run by k_prep) ----------------
__device__ __forceinline__ void gsync(unsigned round) {
    __syncthreads();
    if (threadIdx.x == 0) {
        __threadfence();
        atomicAdd(&g_arrive, 1u);
        unsigned target = round * (unsigned)NBLOCKS;
        volatile unsigned* va = &g_arrive;
        while (*va < target) {}
        __threadfence();
    }
    __syncthreads();
}

// ---------------- ballot-free hot-path quad processing ----------------
__device__ __forceinline__ void proc_quad(float4 d, unsigned qi, float cthr,
                                          float* s_st_s, unsigned* s_st_e, unsigned* s_cnt) {
    float mq = fmaxf(fmaxf(d.x, d.y), fmaxf(d.z, d.w));
    if (mq > cthr) {   // rare (per-lane ~6%): diverge, few active lanes
        unsigned nh = (d.x > cthr) + (d.y > cthr) + (d.z > cthr) + (d.w > cthr);
        unsigned slot = atomicAdd(s_cnt, nh);
        unsigned e = qi << 2;
        if (d.x > cthr) { if (slot < SCAP) { s_st_s[slot] = d.x; s_st_e[slot] = e;      } slot++; }
        if (d.y > cthr) { if (slot < SCAP) { s_st_s[slot] = d.y; s_st_e[slot] = e + 1u; } slot++; }
        if (d.z > cthr) { if (slot < SCAP) { s_st_s[slot] = d.z; s_st_e[slot] = e + 2u; } slot++; }
        if (d.w > cthr) { if (slot < SCAP) { s_st_s[slot] = d.w; s_st_e[slot] = e + 3u; } }
    }
}

// ---------------- the persistent kernel ----------------
__global__ void __launch_bounds__(NTHREADS, 4)
k_main(const float* __restrict__ sc, const float* __restrict__ refw,
       const float* __restrict__ srcw, float* __restrict__ out) {
    __shared__ float    s_st_s[SCAP];
    __shared__ unsigned s_st_e[SCAP];
    __shared__ float    s_cv[CCAP];
    __shared__ int      s_ci[CCAP];
    __shared__ unsigned sh[49];
    __shared__ float    gs[49];
    __shared__ unsigned s_cnt, s_ccnt, s_base, s_n, s_chunk;
    __shared__ float    s_thr;
    __shared__ int      s_need;

    const unsigned tid = threadIdx.x;
    const unsigned lane = tid & 31u;
    const unsigned gtid = blockIdx.x * NTHREADS + tid;
    if (tid < 49) { sh[tid] = 0; gs[tid] = g_grid[tid]; }
    if (tid == 0) { s_cnt = 0; s_ccnt = 0; }
    const float wcap = g_wcap;
    const float cthr = wcap - (finv(g_maxkey_lr) + finv(g_maxkey_ls)) - 1e-4f;
    const float4* __restrict__ p4 = (const float4*)sc;
    __syncthreads();

    // ================= Phase 1: coalesced ballot-free scan =================
    {
        unsigned base = 0;
        for (; base + 4u * TTOT <= NQ4; base += 4u * TTOT) {
            unsigned q0 = base + gtid;
            float4 d0 = p4[q0];
            float4 d1 = p4[q0 + TTOT];
            float4 d2 = p4[q0 + 2u * TTOT];
            float4 d3 = p4[q0 + 3u * TTOT];
            proc_quad(d0, q0,             cthr, s_st_s, s_st_e, &s_cnt);
            proc_quad(d1, q0 + TTOT,      cthr, s_st_s, s_st_e, &s_cnt);
            proc_quad(d2, q0 + 2u * TTOT, cthr, s_st_s, s_st_e, &s_cnt);
            proc_quad(d3, q0 + 3u * TTOT, cthr, s_st_s, s_st_e, &s_cnt);
        }
        for (; base + TTOT <= NQ4; base += TTOT) {
            unsigned q0 = base + gtid;
            float4 d = p4[q0];
            proc_quad(d, q0, cthr, s_st_s, s_st_e, &s_cnt);
        }
        if (base < NQ4) {
            unsigned q0 = base + gtid;
            if (q0 < NQ4) {
                float4 d = p4[q0];
                proc_quad(d, q0, cthr, s_st_s, s_st_e, &s_cnt);
            }
        }
    }
    __syncthreads();

    // ================= Phase 1b: process staged hits =================
    {
        unsigned nst = s_cnt;
        if (nst > SCAP) { if (tid == 0) atomicExch(&g_ovf, 1u); nst = SCAP; }
        float t48 = gs[48];
        for (unsigned i = tid; i < nst; i += NTHREADS) {
            float s = s_st_s[i];
            unsigned e = s_st_e[i];
            unsigned r = e / 8193u;
            unsigned c = e - r * 8193u;
            float w = s + (g_lr[r] + g_ls[c]);
            if (w > wcap) {
                float v = expf(s) * (refw[r] * srcw[c]);
                if (v > t48) {
                    int lo = 0, hi = 48;
                    while (lo < hi) { int mid = (lo + hi) >> 1; if (gs[mid] < v) hi = mid; else lo = mid + 1; }
                    atomicAdd(&sh[lo], 1u);
                }
                unsigned slot = atomicAdd(&s_ccnt, 1u);
                if (slot < CCAP) { s_cv[slot] = v; s_ci[slot] = ((int)r << 13) | (int)c; }
            }
        }
        __syncthreads();
        if (tid == 0) {
            unsigned nc = s_ccnt;
            if (nc > CCAP) { atomicExch(&g_ovf, 1u); nc = CCAP; }
            s_n = nc;
            s_base = nc ? atomicAdd(&g_cand_count, nc) : 0u;
        }
        __syncthreads();
        unsigned nc = s_n, gb = s_base;
        for (unsigned i = tid; i < nc; i += NTHREADS) {
            unsigned slot = gb + i;
            if (slot < CAP) { g_cand_v[slot] = s_cv[i]; g_cand_idx[slot] = s_ci[i]; }
        }
        if (tid < 49 && sh[tid]) atomicAdd(&g_hist[tid], sh[tid]);
    }
    gsync(1);

    // ================= threshold decision =================
    if (tid == 0) {
        unsigned cum = 0; int kstar = -1;
        for (int k = 0; k <= 44; k++) { cum += g_hist[k]; if (cum >= KCORR) { kstar = k; break; } }
        bool bad = (g_ovf != 0u) || (g_cand_count > CAP) || (kstar < 0);
        s_need = bad ? 1 : 0;
        s_thr = (kstar >= 0) ? gs[kstar] : 0.0f;
    }
    __syncthreads();

    if (!s_need) {
        // ============== primary select + output defaults ==============
        float thr = s_thr;
        if (gtid < 2u * MAXC)      out[gtid] = -1.0f;
        else if (gtid < 3u * MAXC) out[gtid] = 0.0f;

        unsigned n = g_cand_count;
        unsigned wbase = gtid - lane;
        for (unsigned b = wbase; b < n; b += TTOT) {
            unsigned i = b + lane;
            bool pred = false; float v = 0.0f; int ix = 0;
            if (i < n) { v = g_cand_v[i]; ix = g_cand_idx[i]; pred = (v > thr); }
            unsigned m = __ballot_sync(0xffffffffu, pred);
            if (m) {
                unsigned base;
                int leader = __ffs(m) - 1;
                if ((int)lane == leader) base = atomicAdd(&g_sel_count, (unsigned)__popc(m));
                base = __shfl_sync(0xffffffffu, base, leader);
                if (pred) {
                    unsigned slot = base + __popc(m & ((1u << lane) - 1u));
                    if (slot < CAP) { g_sel_v[slot] = v; g_sel_idx[slot] = ix; }
                }
            }
        }
        gsync(2);
    } else {
        // ============== fallback: exact full histogram ==============
        if (tid < 49) sh[tid] = 0;
        float t48 = gs[48], t49 = g_grid[49], t50 = g_grid[50];
        float W48m = g_W48m, W49p = g_W49p, W49m = g_W49m, W50p = g_W50p, W50m = g_W50m;
        int t50pos = g_t50pos;
        unsigned c49 = 0, c50 = 0;
        for (;;) {
            if (tid == 0) s_chunk = atomicAdd(&g_work2, 1u);
            __syncthreads();
            unsigned c = s_chunk;
            __syncthreads();
            if (c >= NCHUNK) break;
            unsigned start = c * CHUNK;
            unsigned r0 = start / 8193u;
            unsigned b1 = (r0 + 1u) * 8193u, b2 = b1 + 8193u;
            float lr0 = g_lr[r0];
            float lr1 = g_lr[r0 + 1u <= (unsigned)NI ? r0 + 1u : (unsigned)NI];
            float lr2 = g_lr[r0 + 2u <= (unsigned)NI ? r0 + 2u : (unsigned)NI];
            for (int k = 0; k < 4; k++) {
                unsigned e0 = start + (unsigned)k * 4096u + tid * 16u;
                for (int ii = 0; ii < 16; ii++) {
                    unsigned e = e0 + (unsigned)ii;
                    if (e >= 67117056u) continue;
                    float s = sc[e];
                    int ge1 = (e >= b1), ge2 = (e >= b2);
                    unsigned r = r0 + (unsigned)ge1 + (unsigned)ge2;
                    float lr = ge2 ? lr2 : (ge1 ? lr1 : lr0);
                    unsigned cc = e - r * 8193u;
                    float w = s + (lr + g_ls[cc]);
                    float v = 0.0f; bool havev = false;
                    if (w > W48m) {
                        v = expf(s) * (refw[r] * srcw[cc]); havev = true;
                        if (v > t48) {
                            int lo = 0, hi = 48;
                            while (lo < hi) { int mid = (lo + hi) >> 1; if (gs[mid] < v) hi = mid; else lo = mid + 1; }
                            atomicAdd(&sh[lo], 1u);
                        }
                    }
                    if (w > W49p) c49++;
                    else if (w > W49m) {
                        if (!havev) { v = expf(s) * (refw[r] * srcw[cc]); havev = true; }
                        if (v > t49) c49++;
                    }
                    if (t50pos) {
                        if (w > W50p) c50++;
                        else if (w > W50m) {
                            if (!havev) { v = expf(s) * (refw[r] * srcw[cc]); }
                            if (v > t50) c50++;
                        }
                    } else c50++;
                }
            }
        }
        if (c49) atomicAdd(&g_c49, c49);
        if (c50) atomicAdd(&g_c50, c50);
        if (tid < 49 && sh[tid]) atomicAdd(&g_hist2[tid], sh[tid]);
        gsync(2);

        if (tid == 0) {
            unsigned cum = 0; int kstar = -1;
            for (int k = 0; k <= 48; k++) { cum += g_hist2[k]; if (cum >= KCORR) { kstar = k; break; } }
            if (kstar < 0) {
                if (g_c49 >= KCORR) kstar = 49;
                else if (g_c50 >= KCORR) kstar = 50;
                else kstar = 51;
            }
            s_thr = g_grid[kstar];
        }
        __syncthreads();
        float thr = s_thr;
        float wf = (thr > 0.0f) ? (logf(thr) - 0.005f) : -3.0e38f;

        if (gtid < 2u * MAXC)      out[gtid] = -1.0f;
        else if (gtid < 3u * MAXC) out[gtid] = 0.0f;

        // full-matrix select (reuses staging arrays)
        for (;;) {
            if (tid == 0) { s_chunk = atomicAdd(&g_work3, 1u); s_cnt = 0; }
            __syncthreads();
            unsigned c = s_chunk;
            if (c >= NCHUNK) break;
            unsigned start = c * CHUNK;
            unsigned r0 = start / 8193u;
            unsigned b1 = (r0 + 1u) * 8193u, b2 = b1 + 8193u;
            float lr0 = g_lr[r0];
            float lr1 = g_lr[r0 + 1u <= (unsigned)NI ? r0 + 1u : (unsigned)NI];
            float lr2 = g_lr[r0 + 2u <= (unsigned)NI ? r0 + 2u : (unsigned)NI];
            for (int k = 0; k < 4; k++) {
                unsigned e0 = start + (unsigned)k * 4096u + tid * 16u;
                for (int ii = 0; ii < 16; ii++) {
                    unsigned e = e0 + (unsigned)ii;
                    if (e >= 67117056u) continue;
                    float s = sc[e];
                    int ge1 = (e >= b1), ge2 = (e >= b2);
                    unsigned r = r0 + (unsigned)ge1 + (unsigned)ge2;
                    float lr = ge2 ? lr2 : (ge1 ? lr1 : lr0);
                    unsigned cc = e - r * 8193u;
                    float w = s + (lr + g_ls[cc]);
                    if (w > wf) {
                        float v = expf(s) * (refw[r] * srcw[cc]);
                        if (v > thr) {
                            unsigned slot = atomicAdd(&s_cnt, 1u);
                            if (slot < SCAP) { s_st_s[slot] = v; s_st_e[slot] = (r << 13) | cc; }
                        }
                    }
                }
            }
            __syncthreads();
            if (tid == 0) {
                unsigned nn = s_cnt;
                unsigned ncl = nn < SCAP ? nn : SCAP;
                s_base = ncl ? atomicAdd(&g_sel_count, ncl) : 0u;
                s_n = ncl;
            }
            __syncthreads();
            unsigned ncl = s_n, gb = s_base;
            for (unsigned i = tid; i < ncl; i += NTHREADS) {
                unsigned slot = gb + i;
                if (slot < CAP) { g_sel_v[slot] = s_st_s[i]; g_sel_idx[slot] = (int)s_st_e[i]; }
            }
            __syncthreads();
        }
        gsync(3);
    }

    // ================= rank (row-major order) + write =================
    unsigned S = g_sel_count; if (S > CAP) S = CAP;
    unsigned t = gtid;
    if (blockIdx.x * NTHREADS >= S) return;
    bool act = (t < S);
    int my = 0; float v = 0.0f;
    if (act) { my = g_sel_idx[t]; v = g_sel_v[t]; }
    int* tile = (int*)s_st_e;
    unsigned rank = 0;
    for (unsigned base = 0; base < S; base += SCAP) {
        unsigned n = S - base; if (n > SCAP) n = SCAP;
        __syncthreads();
        for (unsigned i = tid; i < n; i += NTHREADS) tile[i] = g_sel_idx[base + i];
        __syncthreads();
        if (act) {
            unsigned i = 0;
            for (; i + 4 <= n; i += 4)
                rank += (tile[i] < my) + (tile[i+1] < my) + (tile[i+2] < my) + (tile[i+3] < my);
            for (; i < n; i++) rank += (tile[i] < my);
        }
    }
    if (act && rank < MAXC) {
        out[rank]            = (float)(my >> 13);
        out[MAXC + rank]     = (float)(my & 8191);
        out[2 * MAXC + rank] = v;
    }
}

// ---------------- launch ----------------
extern "C" void kernel_launch(void* const* d_in, const int* in_sizes, int n_in,
                              void* d_out, int out_size) {
    const float* sc   = (const float*)d_in[0];
    const float* refw = (const float*)d_in[1];
    const float* srcw = (const float*)d_in[2];
    float* out = (float*)d_out;

    k_prep<<<64, 256>>>(refw, srcw);
    k_main<<<NBLOCKS, NTHREADS>>>(sc, refw, srcw, out);
}